// round 1
// baseline (speedup 1.0000x reference)
#include <cuda_runtime.h>
#include <cuda_bf16.h>

// RAM multi-step transformer (weightless LUT network).
// x:          (256, 1024) int32 bits
// conn_in:    (2048, 16)  int32 idx into [0,1024)
// conn_state: (1024, 16)  int32 idx into [0,3072)
// conn_out:   (512, 16)   int32 idx into [0,3072)
// mem_in:     (2048, 65536) f32
// mem_state:  (1024, 65536) f32
// mem_out:    (512, 65536)  f32
// out:        (256, 512) f32
//
// One CTA per batch element; all bit state lives in shared memory as bytes.
// Only the LAST iteration's output lookup survives in the reference, so the
// out phase runs once.

#define NB 16
#define BATCH 256
#define IN_BITS 1024
#define N_IN 2048
#define N_ST 1024
#define N_OUT 512
#define TBL 65536
#define MAX_ITERS 4
#define THREADS 256

// Build a 16-bit address from 16 byte-flags in shared memory.
#define GATHER_ADDR(bits, c0, c1, c2, c3)                       \
    (((unsigned)(bits)[(c0).x] << 0)  | ((unsigned)(bits)[(c0).y] << 1)  |   \
     ((unsigned)(bits)[(c0).z] << 2)  | ((unsigned)(bits)[(c0).w] << 3)  |   \
     ((unsigned)(bits)[(c1).x] << 4)  | ((unsigned)(bits)[(c1).y] << 5)  |   \
     ((unsigned)(bits)[(c1).z] << 6)  | ((unsigned)(bits)[(c1).w] << 7)  |   \
     ((unsigned)(bits)[(c2).x] << 8)  | ((unsigned)(bits)[(c2).y] << 9)  |   \
     ((unsigned)(bits)[(c2).z] << 10) | ((unsigned)(bits)[(c2).w] << 11) |   \
     ((unsigned)(bits)[(c3).x] << 12) | ((unsigned)(bits)[(c3).y] << 13) |   \
     ((unsigned)(bits)[(c3).z] << 14) | ((unsigned)(bits)[(c3).w] << 15))

__global__ __launch_bounds__(THREADS, 2)
void ram_multistep_kernel(
    const int* __restrict__ x,
    const int4* __restrict__ conn_in,
    const int4* __restrict__ conn_state,
    const int4* __restrict__ conn_out,
    const float* __restrict__ mem_in,
    const float* __restrict__ mem_state,
    const float* __restrict__ mem_out,
    float* __restrict__ out)
{
    __shared__ unsigned char sx[IN_BITS];          // input bits as bytes
    __shared__ unsigned char sbits[N_IN + N_ST];   // [0,2048) in_bits, [2048,3072) state
    __shared__ unsigned char snew[N_ST];           // double buffer for state update

    const int b = blockIdx.x;
    const int tid = threadIdx.x;

    // Load this batch element's input bits into shared as bytes.
    {
        const int4* xb = reinterpret_cast<const int4*>(x + b * IN_BITS);
        #pragma unroll
        for (int r = 0; r < IN_BITS / 4 / THREADS; r++) {
            int i = r * THREADS + tid;
            int4 v = __ldg(xb + i);
            sx[i * 4 + 0] = (unsigned char)v.x;
            sx[i * 4 + 1] = (unsigned char)v.y;
            sx[i * 4 + 2] = (unsigned char)v.z;
            sx[i * 4 + 3] = (unsigned char)v.w;
        }
        // init state bits to 0
        #pragma unroll
        for (int r = 0; r < N_ST / THREADS; r++)
            sbits[N_IN + r * THREADS + tid] = 0;
    }
    __syncthreads();

    // ---- Phase 1: input-layer lookups (2048 neurons, 8 per thread) ----
    #pragma unroll
    for (int r = 0; r < N_IN / THREADS; r++) {
        int n = r * THREADS + tid;
        const int4* c = conn_in + n * 4;
        int4 c0 = __ldg(c + 0), c1 = __ldg(c + 1), c2 = __ldg(c + 2), c3 = __ldg(c + 3);
        unsigned addr = GATHER_ADDR(sx, c0, c1, c2, c3);
        float v = __ldg(mem_in + (size_t)n * TBL + addr);
        sbits[n] = (v > 0.5f) ? 1 : 0;
    }
    __syncthreads();

    // ---- Phase 2: recurrent state iterations ----
    for (int it = 0; it < MAX_ITERS; it++) {
        #pragma unroll
        for (int r = 0; r < N_ST / THREADS; r++) {
            int n = r * THREADS + tid;
            const int4* c = conn_state + n * 4;
            int4 c0 = __ldg(c + 0), c1 = __ldg(c + 1), c2 = __ldg(c + 2), c3 = __ldg(c + 3);
            unsigned addr = GATHER_ADDR(sbits, c0, c1, c2, c3);
            float v = __ldg(mem_state + (size_t)n * TBL + addr);
            snew[n] = (v > 0.5f) ? 1 : 0;
        }
        __syncthreads();
        #pragma unroll
        for (int r = 0; r < N_ST / THREADS; r++) {
            int i = r * THREADS + tid;
            sbits[N_IN + i] = snew[i];
        }
        __syncthreads();
    }

    // ---- Phase 3: output lookups (only the last iteration's result survives) ----
    #pragma unroll
    for (int r = 0; r < N_OUT / THREADS; r++) {
        int n = r * THREADS + tid;
        const int4* c = conn_out + n * 4;
        int4 c0 = __ldg(c + 0), c1 = __ldg(c + 1), c2 = __ldg(c + 2), c3 = __ldg(c + 3);
        unsigned addr = GATHER_ADDR(sbits, c0, c1, c2, c3);
        out[b * N_OUT + n] = __ldg(mem_out + (size_t)n * TBL + addr);
    }
}

extern "C" void kernel_launch(void* const* d_in, const int* in_sizes, int n_in,
                              void* d_out, int out_size) {
    const int* x            = (const int*)d_in[0];
    const int4* conn_in     = (const int4*)d_in[1];
    const int4* conn_state  = (const int4*)d_in[2];
    const int4* conn_out    = (const int4*)d_in[3];
    const float* mem_in     = (const float*)d_in[4];
    const float* mem_state  = (const float*)d_in[5];
    const float* mem_out    = (const float*)d_in[6];
    float* out = (float*)d_out;

    ram_multistep_kernel<<<BATCH, THREADS>>>(x, conn_in, conn_state, conn_out,
                                             mem_in, mem_state, mem_out, out);
}